// round 13
// baseline (speedup 1.0000x reference)
#include <cuda_runtime.h>
#include <cuda_bf16.h>
#include <math.h>
#include <stdint.h>

// ---------------- problem constants ----------------
#define SEQ     2048
#define DM      768
#define DIP     3224
#define DINNER  1536
#define CONVCH  1664
#define NHEADS  24
#define HD      64
#define DSTATE  64
#define DCONV   4
#define FFN     2048
#define EPS1    1.1920929e-07f
#define EPSG    1e-5f

// ---------------- fp32 scratch arena ----------------
constexpr size_t SZ_XN  = (size_t)SEQ * DM;
constexpr size_t SZ_ZX  = (size_t)SEQ * DIP;
constexpr size_t SZ_XBC = (size_t)SEQ * CONVCH;
constexpr size_t SZ_DT  = (size_t)SEQ * NHEADS;
constexpr size_t SZ_DA  = (size_t)SEQ * NHEADS;
constexpr size_t SZ_Y   = (size_t)SEQ * DINNER;
constexpr size_t SZ_G   = (size_t)SEQ * FFN;

constexpr size_t OFF_XN  = 0;
constexpr size_t OFF_ZX  = OFF_XN  + SZ_XN;
constexpr size_t OFF_XBC = OFF_ZX  + SZ_ZX;
constexpr size_t OFF_DT  = OFF_XBC + SZ_XBC;
constexpr size_t OFF_DA  = OFF_DT  + SZ_DT;
constexpr size_t OFF_Y   = OFF_DA  + SZ_DA;
constexpr size_t OFF_X1  = OFF_Y   + SZ_Y;
constexpr size_t OFF_H   = OFF_X1  + SZ_XN;
constexpr size_t OFF_G   = OFF_H   + SZ_XN;
constexpr size_t TOTAL_F = OFF_G   + SZ_G;

__device__ float g_buf[TOTAL_F];

// ---------------- bf16 hi/lo arena ----------------
constexpr size_t N_W_IN   = (size_t)DIP * DM;
constexpr size_t N_W_OUT  = (size_t)DM * DINNER;
constexpr size_t N_W_GATE = (size_t)FFN * DM;
constexpr size_t N_W_UP   = (size_t)FFN * DM;
constexpr size_t N_W_DOWN = (size_t)DM * FFN;
constexpr size_t N_XN = SZ_XN;
constexpr size_t N_Y  = SZ_Y;
constexpr size_t N_H  = SZ_XN;
constexpr size_t N_G  = SZ_G;

constexpr size_t BF_W_IN   = 0;
constexpr size_t BF_W_OUT  = BF_W_IN   + 2 * N_W_IN;
constexpr size_t BF_W_GATE = BF_W_OUT  + 2 * N_W_OUT;
constexpr size_t BF_W_UP   = BF_W_GATE + 2 * N_W_GATE;
constexpr size_t BF_W_DOWN = BF_W_UP   + 2 * N_W_UP;
constexpr size_t BF_XN     = BF_W_DOWN + 2 * N_W_DOWN;
constexpr size_t BF_Y      = BF_XN     + 2 * N_XN;
constexpr size_t BF_H      = BF_Y      + 2 * N_Y;
constexpr size_t BF_G      = BF_H      + 2 * N_H;
constexpr size_t TOTAL_BF  = BF_G      + 2 * N_G;

__device__ __align__(256) __nv_bfloat16 g_bf[TOTAL_BF];

__device__ __forceinline__ const float* RP(const float* p, size_t off) {
    return p ? p : (const float*)g_buf + off;
}
__device__ __forceinline__ float* WP(float* p, size_t off) {
    return p ? p : g_buf + off;
}
__device__ __forceinline__ float siluf(float v) { return v / (1.0f + expf(-v)); }

__device__ __forceinline__ void bf_split(float x, __nv_bfloat16& h, __nv_bfloat16& l) {
    h = __float2bfloat16(x);
    l = __float2bfloat16(x - __bfloat162float(h));
}

// ---------------- PTX helpers ----------------
__device__ __forceinline__ uint32_t smem_u32(const void* p) {
    uint32_t a;
    asm("{ .reg .u64 t; cvta.to.shared.u64 t, %1; cvt.u32.u64 %0, t; }" : "=r"(a) : "l"(p));
    return a;
}
#define CP_ASYNC16(dst, src, sz) \
    asm volatile("cp.async.cg.shared.global [%0], [%1], 16, %2;" \
        :: "r"(dst), "l"(src), "r"(sz) : "memory")
#define CP_COMMIT() asm volatile("cp.async.commit_group;" ::: "memory")
#define CP_WAITG(n) asm volatile("cp.async.wait_group %0;" :: "n"(n) : "memory")

__device__ __forceinline__ void ldsm4(uint32_t* r, uint32_t addr) {
    asm volatile("ldmatrix.sync.aligned.m8n8.x4.shared.b16 {%0,%1,%2,%3}, [%4];"
        : "=r"(r[0]), "=r"(r[1]), "=r"(r[2]), "=r"(r[3]) : "r"(addr));
}
__device__ __forceinline__ void mma16(float (&c)[4], const uint32_t* a,
                                      uint32_t b0, uint32_t b1) {
    asm volatile(
        "mma.sync.aligned.m16n8k16.row.col.f32.bf16.bf16.f32 "
        "{%0,%1,%2,%3},{%4,%5,%6,%7},{%8,%9},{%0,%1,%2,%3};"
        : "+f"(c[0]), "+f"(c[1]), "+f"(c[2]), "+f"(c[3])
        : "r"(a[0]), "r"(a[1]), "r"(a[2]), "r"(a[3]), "r"(b0), "r"(b1));
}

// ---------------- fp32 -> bf16 hi/lo conversion ----------------
__global__ __launch_bounds__(256) void f2bf_kernel(
    const float* __restrict__ ext, size_t soff, size_t bfoff, size_t n)
{
    const float4* src = (const float4*)(RP(ext, soff));
    __nv_bfloat16* hi = g_bf + bfoff;
    __nv_bfloat16* lo = hi + n;
    size_t n4 = n >> 2;
    for (size_t i = (size_t)blockIdx.x * 256 + threadIdx.x; i < n4;
         i += (size_t)gridDim.x * 256) {
        float4 v = src[i];
        __nv_bfloat16 h0, l0, h1, l1, h2, l2, h3, l3;
        bf_split(v.x, h0, l0); bf_split(v.y, h1, l1);
        bf_split(v.z, h2, l2); bf_split(v.w, h3, l3);
        ((ushort4*)hi)[i] = make_ushort4(__bfloat16_as_ushort(h0), __bfloat16_as_ushort(h1),
                                         __bfloat16_as_ushort(h2), __bfloat16_as_ushort(h3));
        ((ushort4*)lo)[i] = make_ushort4(__bfloat16_as_ushort(l0), __bfloat16_as_ushort(l1),
                                         __bfloat16_as_ushort(l2), __bfloat16_as_ushort(l3));
    }
}

// ---------------- block reduce ----------------
__device__ __forceinline__ float blockReduceSum(float v) {
    __shared__ float sh[32];
    int lane = threadIdx.x & 31, wid = threadIdx.x >> 5;
    #pragma unroll
    for (int o = 16; o; o >>= 1) v += __shfl_xor_sync(0xffffffffu, v, o);
    if (lane == 0) sh[wid] = v;
    __syncthreads();
    if (wid == 0) {
        v = (lane < (int)(blockDim.x >> 5)) ? sh[lane] : 0.0f;
        #pragma unroll
        for (int o = 16; o; o >>= 1) v += __shfl_xor_sync(0xffffffffu, v, o);
        if (lane == 0) sh[0] = v;
    }
    __syncthreads();
    return sh[0];
}

// ---------------- RMSNorm (optional fused bf16 hi/lo output) ----------------
__global__ __launch_bounds__(256) void rmsnorm_kernel(
    const float* __restrict__ xe, size_t xoff,
    const float* __restrict__ w,
    float* __restrict__ oe, size_t ooff,
    size_t bfoff, size_t bfn,
    int C, float eps)
{
    const float* x = RP(xe, xoff) + (size_t)blockIdx.x * C;
    float* o = WP(oe, ooff) + (size_t)blockIdx.x * C;
    float ss = 0.0f;
    for (int i = threadIdx.x; i < C; i += 256) { float v = x[i]; ss += v * v; }
    float tot = blockReduceSum(ss);
    float scale = rsqrtf(tot / (float)C + eps);
    __nv_bfloat16* hi = g_bf + bfoff + (size_t)blockIdx.x * C;
    __nv_bfloat16* lo = hi + bfn;
    for (int i = threadIdx.x; i < C; i += 256) {
        float v = x[i] * scale * w[i];
        o[i] = v;
        if (bfn) { __nv_bfloat16 h, l; bf_split(v, h, l); hi[i] = h; lo[i] = l; }
    }
}

// ---------------- Gated RMSNorm -> bf16 y ----------------
__global__ __launch_bounds__(256) void gated_norm_kernel(const float* __restrict__ w)
{
    __shared__ float sv[DINNER];
    size_t r = blockIdx.x;
    const float* y = g_buf + OFF_Y + r * DINNER;
    const float* z = g_buf + OFF_ZX + r * DIP;
    float ss = 0.0f;
    for (int i = threadIdx.x; i < DINNER; i += 256) {
        float v = y[i] * siluf(z[i]);
        sv[i] = v;
        ss += v * v;
    }
    float tot = blockReduceSum(ss);
    float scale = rsqrtf(tot / (float)DINNER + EPSG);
    __nv_bfloat16* hi = g_bf + BF_Y + r * DINNER;
    __nv_bfloat16* lo = hi + N_Y;
    for (int i = threadIdx.x; i < DINNER; i += 256) {
        float v = sv[i] * scale * w[i];
        __nv_bfloat16 h, l; bf_split(v, h, l);
        hi[i] = h; lo[i] = l;
    }
}

// ---------------- causal depthwise conv4 + bias + SiLU ----------------
__global__ __launch_bounds__(256) void conv_silu_kernel(
    const float* __restrict__ cw, const float* __restrict__ cb)
{
    int gid = blockIdx.x * 256 + threadIdx.x;
    if (gid >= SEQ * CONVCH) return;
    int c = gid % CONVCH;
    int t = gid / CONVCH;
    const float* zx = g_buf + OFF_ZX;
    float v = cb[c];
    #pragma unroll
    for (int k = 0; k < DCONV; k++) {
        int tt = t + k - (DCONV - 1);
        if (tt >= 0) v += zx[(size_t)tt * DIP + DINNER + c] * cw[c * DCONV + k];
    }
    g_buf[OFF_XBC + (size_t)t * CONVCH + c] = siluf(v);
}

// ---------------- dt from zxbcdt (computed by split-GEMM) ----------------
__global__ __launch_bounds__(256) void dt_kernel(
    const float* __restrict__ dt_bias, const float* __restrict__ A_log)
{
    int gid = blockIdx.x * 256 + threadIdx.x;
    if (gid >= SEQ * NHEADS) return;
    int h = gid % NHEADS;
    int t = gid / NHEADS;
    float v = g_buf[OFF_ZX + (size_t)t * DIP + DINNER + CONVCH + h] + dt_bias[h];
    float dt = (v > 20.f) ? v : log1pf(expf(v));
    g_buf[OFF_DT + (size_t)t * NHEADS + h] = dt;
    g_buf[OFF_DA + (size_t)t * NHEADS + h] = expf(dt * (-expf(A_log[h])));
}

// ---------------- SSM scan (register pipelined, barrier-free) ----------------
__global__ __launch_bounds__(256) void scan_kernel(const float* __restrict__ Dv)
{
    const int b   = blockIdx.x;
    const int h   = b >> 2;
    const int ps  = b & 3;
    const int tid = threadIdx.x;
    const int pl  = tid >> 4;
    const int nq  = tid & 15;
    const int p   = ps * 16 + pl;
    const int n0  = nq * 4;
    const float Dh = Dv[h];

    const float* xbc = g_buf + OFF_XBC;
    const float* dtb = g_buf + OFF_DT;
    const float* dab = g_buf + OFF_DA;
    float* yb = g_buf + OFF_Y;

    const float* Bcol = xbc + DINNER + n0;
    const float* Ccol = xbc + DINNER + DSTATE + n0;
    const float* Xcol = xbc + h * HD + p;

    constexpr int PF = 8;
    float4 rB[PF], rC[PF];
    float rx[PF], rdt[PF], rdA[PF];

    #pragma unroll
    for (int i = 0; i < PF; i++) {
        rB[i]  = *(const float4*)(Bcol + (size_t)i * CONVCH);
        rC[i]  = *(const float4*)(Ccol + (size_t)i * CONVCH);
        rx[i]  = Xcol[(size_t)i * CONVCH];
        rdt[i] = dtb[(size_t)i * NHEADS + h];
        rdA[i] = dab[(size_t)i * NHEADS + h];
    }

    float s0 = 0.f, s1 = 0.f, s2 = 0.f, s3 = 0.f;
    const bool writer = (nq == 0);

    for (int t = 0; t < SEQ; t += PF) {
        #pragma unroll
        for (int u = 0; u < PF; u++) {
            float dA = rdA[u], dt = rdt[u], x = rx[u];
            float4 Bv = rB[u], Cv = rC[u];
            int tn = t + u + PF;
            if (tn < SEQ) {
                rB[u]  = *(const float4*)(Bcol + (size_t)tn * CONVCH);
                rC[u]  = *(const float4*)(Ccol + (size_t)tn * CONVCH);
                rx[u]  = Xcol[(size_t)tn * CONVCH];
                rdt[u] = dtb[(size_t)tn * NHEADS + h];
                rdA[u] = dab[(size_t)tn * NHEADS + h];
            }
            float dtx = dt * x;
            s0 = s0 * dA + dtx * Bv.x; float acc = s0 * Cv.x;
            s1 = s1 * dA + dtx * Bv.y; acc += s1 * Cv.y;
            s2 = s2 * dA + dtx * Bv.z; acc += s2 * Cv.z;
            s3 = s3 * dA + dtx * Bv.w; acc += s3 * Cv.w;
            acc += __shfl_xor_sync(0xffffffffu, acc, 1);
            acc += __shfl_xor_sync(0xffffffffu, acc, 2);
            acc += __shfl_xor_sync(0xffffffffu, acc, 4);
            acc += __shfl_xor_sync(0xffffffffu, acc, 8);
            if (writer)
                yb[(size_t)(t + u) * DINNER + h * HD + p] = acc + Dh * x;
        }
    }
}

// ---------------- bf16-split HMMA GEMM (4-stage cp.async, 1 sync/chunk) ----------------
// O[M,N] = A[M,K] @ W[N,K]^T.  modes: 0 = fp32 out, 1 = fp32 out + residual,
// 2 = swiglu: v = silu(R[fp32]) * acc -> bf16 hi/lo into g_bf at ooff (count bfn).
#define RS 80
#define NSTG 4

template<int BM>
__global__ __launch_bounds__(256) void gemm_bf(
    size_t a_hi, size_t a_n,
    size_t w_hi, size_t w_n,
    const float* __restrict__ Re, size_t roff,
    float* __restrict__ Oe, size_t ooff, size_t bfn,
    int mode, int M, int N, int K)
{
    constexpr int TI = BM / 32;               // warp-row tiles of 16
    constexpr int ABUF = BM * RS;
    constexpr int BBUF = 128 * RS;
    constexpr int STAGE = 2 * ABUF + 2 * BBUF;

    extern __shared__ char smem[];
    const uint32_t sb = smem_u32(smem);
    const int tid  = threadIdx.x;
    const int lane = tid & 31;
    const int wid  = tid >> 5;
    const int wm   = (wid & 1) * (BM / 2);
    const int wn   = (wid >> 1) * 32;
    const int bm   = blockIdx.y * BM;
    const int bn   = blockIdx.x * 128;
    const int g    = lane >> 2;
    const int cc   = lane & 3;

    const __nv_bfloat16* Ah = g_bf + a_hi;
    const __nv_bfloat16* Al = Ah + a_n;
    const __nv_bfloat16* Wh = g_bf + w_hi;
    const __nv_bfloat16* Wl = Wh + w_n;

    const int l15 = lane & 15;
    const int lhi = (lane >> 4) & 1;
    const uint32_t aoff = (uint32_t)((wm + l15) * RS + lhi * 16);
    const uint32_t boff = (uint32_t)(2 * ABUF + (wn + l15) * RS + lhi * 16);

    float acc[TI][4][4];
    #pragma unroll
    for (int i = 0; i < TI; i++)
        #pragma unroll
        for (int j = 0; j < 4; j++)
            #pragma unroll
            for (int q = 0; q < 4; q++) acc[i][j][q] = 0.f;

    const int KT = K >> 5;

    auto issue = [&](int kc) {
        const uint32_t base = sb + (uint32_t)(kc & (NSTG - 1)) * STAGE;
        const size_t kb = (size_t)kc * 32;
        #pragma unroll
        for (int u = tid; u < BM * 4; u += 256) {
            int row = u >> 2, un = u & 3;
            uint32_t d = base + (uint32_t)(row * RS + un * 16);
            size_t gs = (size_t)(bm + row) * K + kb + un * 8;
            CP_ASYNC16(d, Ah + gs, 16);
            CP_ASYNC16(d + ABUF, Al + gs, 16);
        }
        #pragma unroll
        for (int u = tid; u < 512; u += 256) {
            int row = u >> 2, un = u & 3;
            int n = bn + row;
            int sz = (n < N) ? 16 : 0;
            size_t gs = (n < N) ? ((size_t)n * K + kb + un * 8) : 0;
            uint32_t d = base + (uint32_t)(2 * ABUF + row * RS + un * 16);
            CP_ASYNC16(d, Wh + gs, sz);
            CP_ASYNC16(d + BBUF, Wl + gs, sz);
        }
        CP_COMMIT();
    };

    issue(0); issue(1); issue(2);

    for (int kc = 0; kc < KT; kc++) {
        if (kc == KT - 1)      { CP_WAITG(0); }
        else if (kc == KT - 2) { CP_WAITG(1); }
        else                   { CP_WAITG(2); }
        __syncthreads();
        if (kc + 3 < KT) issue(kc + 3);

        const uint32_t base = sb + (uint32_t)(kc & (NSTG - 1)) * STAGE;
        #pragma unroll
        for (int s = 0; s < 2; s++) {
            uint32_t ah[TI][4], al[TI][4], bh[2][4], bl[2][4];
            #pragma unroll
            for (int i = 0; i < TI; i++) {
                uint32_t ad = base + aoff + i * (16 * RS) + s * 32;
                ldsm4(ah[i], ad);
                ldsm4(al[i], ad + ABUF);
            }
            #pragma unroll
            for (int jp = 0; jp < 2; jp++) {
                uint32_t bd = base + boff + jp * (16 * RS) + s * 32;
                ldsm4(bh[jp], bd);
                ldsm4(bl[jp], bd + BBUF);
            }
            #pragma unroll
            for (int i = 0; i < TI; i++) {
                #pragma unroll
                for (int j = 0; j < 4; j++) {
                    int jp = j >> 1, sel = j & 1;
                    uint32_t b0h = bh[jp][sel], b1h = bh[jp][sel + 2];
                    uint32_t b0l = bl[jp][sel], b1l = bl[jp][sel + 2];
                    mma16(acc[i][j], ah[i], b0h, b1h);
                    mma16(acc[i][j], al[i], b0h, b1h);
                    mma16(acc[i][j], ah[i], b0l, b1l);
                }
            }
        }
    }

    // ---- epilogue ----
    if (mode == 2) {
        const float* G = RP(Re, roff);
        __nv_bfloat16* hi = g_bf + ooff;
        __nv_bfloat16* lo = hi + bfn;
        #pragma unroll
        for (int i = 0; i < TI; i++) {
            int row = bm + wm + i * 16 + g;
            #pragma unroll
            for (int j = 0; j < 4; j++) {
                int col = bn + wn + j * 8 + 2 * cc;
                if (col < N) {
                    #pragma unroll
                    for (int half = 0; half < 2; half++) {
                        int r = row + half * 8;
                        size_t o = (size_t)r * N + col;
                        float2 gv = *(const float2*)(G + o);
                        float v0 = siluf(gv.x) * acc[i][j][half * 2 + 0];
                        float v1 = siluf(gv.y) * acc[i][j][half * 2 + 1];
                        __nv_bfloat16 h0, l0, h1, l1;
                        bf_split(v0, h0, l0); bf_split(v1, h1, l1);
                        *(__nv_bfloat162*)(hi + o) = __nv_bfloat162(h0, h1);
                        *(__nv_bfloat162*)(lo + o) = __nv_bfloat162(l0, l1);
                    }
                }
            }
        }
    } else {
        const float* R = (mode == 1) ? RP(Re, roff) : nullptr;
        float* O = WP(Oe, ooff);
        #pragma unroll
        for (int i = 0; i < TI; i++) {
            int row = bm + wm + i * 16 + g;
            #pragma unroll
            for (int j = 0; j < 4; j++) {
                int col = bn + wn + j * 8 + 2 * cc;
                if (col < N) {
                    size_t o0 = (size_t)row * N + col;
                    size_t o1 = (size_t)(row + 8) * N + col;
                    float2 v0 = make_float2(acc[i][j][0], acc[i][j][1]);
                    float2 v1 = make_float2(acc[i][j][2], acc[i][j][3]);
                    if (mode == 1) {
                        float2 q0 = *(const float2*)(R + o0);
                        float2 q1 = *(const float2*)(R + o1);
                        v0.x += q0.x; v0.y += q0.y;
                        v1.x += q1.x; v1.y += q1.y;
                    }
                    *(float2*)(O + o0) = v0;
                    *(float2*)(O + o1) = v1;
                }
            }
        }
    }
}

constexpr int SMEM_128 = NSTG * (2 * 128 * RS + 2 * 128 * RS);  // 163840
constexpr int SMEM_64  = NSTG * (2 * 64 * RS + 2 * 128 * RS);   // 122880

// ---------------- launch ----------------
extern "C" void kernel_launch(void* const* d_in, const int* in_sizes, int n_in,
                              void* d_out, int out_size)
{
    const float* x          = (const float*)d_in[0];
    const float* norm1_w    = (const float*)d_in[1];
    const float* norm2_w    = (const float*)d_in[2];
    const float* in_proj_w  = (const float*)d_in[3];
    const float* conv_w     = (const float*)d_in[4];
    const float* conv_b     = (const float*)d_in[5];
    const float* dt_bias    = (const float*)d_in[6];
    const float* A_log      = (const float*)d_in[7];
    const float* Dv         = (const float*)d_in[8];
    const float* ssm_norm_w = (const float*)d_in[9];
    const float* out_proj_w = (const float*)d_in[10];
    const float* gate_w     = (const float*)d_in[11];
    const float* up_w       = (const float*)d_in[12];
    const float* down_w     = (const float*)d_in[13];
    float* out = (float*)d_out;

    cudaFuncSetAttribute(gemm_bf<128>, cudaFuncAttributeMaxDynamicSharedMemorySize, SMEM_128);
    cudaFuncSetAttribute(gemm_bf<64>,  cudaFuncAttributeMaxDynamicSharedMemorySize, SMEM_64);

    // launches 1-5 (ncu -s 5 skips these; #6 = in_proj GEMM gets profiled)
    rmsnorm_kernel<<<SEQ, 256>>>(x, 0, norm1_w, nullptr, OFF_XN, BF_XN, N_XN, DM, EPS1);
    f2bf_kernel<<<256, 256>>>(in_proj_w,  0, BF_W_IN,   N_W_IN);
    f2bf_kernel<<<128, 256>>>(out_proj_w, 0, BF_W_OUT,  N_W_OUT);
    f2bf_kernel<<<160, 256>>>(gate_w,     0, BF_W_GATE, N_W_GATE);
    f2bf_kernel<<<160, 256>>>(up_w,       0, BF_W_UP,   N_W_UP);

    // #6: zxbcdt = xn @ in_proj_w^T
    gemm_bf<128><<<dim3((DIP + 127) / 128, SEQ / 128), 256, SMEM_128>>>(
        BF_XN, N_XN, BF_W_IN, N_W_IN, nullptr, 0, nullptr, OFF_ZX, 0, 0, SEQ, DIP, DM);

    f2bf_kernel<<<160, 256>>>(down_w, 0, BF_W_DOWN, N_W_DOWN);

    // conv + silu
    conv_silu_kernel<<<(SEQ * CONVCH + 255) / 256, 256>>>(conv_w, conv_b);

    // dt = softplus(zx_dt + bias), dA = exp(dt*A)
    dt_kernel<<<(SEQ * NHEADS + 255) / 256, 256>>>(dt_bias, A_log);

    // SSM scan
    scan_kernel<<<NHEADS * 4, 256>>>(Dv);

    // gated rmsnorm -> bf16 y
    gated_norm_kernel<<<SEQ, 256>>>(ssm_norm_w);

    // x1 = y @ out_proj_w^T + x   (BM=64: 192 blocks)
    gemm_bf<64><<<dim3(DM / 128, SEQ / 64), 256, SMEM_64>>>(
        BF_Y, N_Y, BF_W_OUT, N_W_OUT, x, 0, nullptr, OFF_X1, 0, 1, SEQ, DM, DINNER);

    // h = rmsnorm(x1) -> bf16
    rmsnorm_kernel<<<SEQ, 256>>>(nullptr, OFF_X1, norm2_w, nullptr, OFF_H, BF_H, N_H, DM, EPS1);

    // g = h @ gate_w^T (fp32)
    gemm_bf<128><<<dim3(FFN / 128, SEQ / 128), 256, SMEM_128>>>(
        BF_H, N_H, BF_W_GATE, N_W_GATE, nullptr, 0, nullptr, OFF_G, 0, 0, SEQ, FFN, DM);

    // u = h @ up_w^T, fused: bfG = split(silu(g) * u)
    gemm_bf<128><<<dim3(FFN / 128, SEQ / 128), 256, SMEM_128>>>(
        BF_H, N_H, BF_W_UP, N_W_UP, nullptr, OFF_G, nullptr, BF_G, N_G, 2, SEQ, FFN, DM);

    // out = bfG @ down_w^T + x1   (BM=64: 192 blocks)
    gemm_bf<64><<<dim3(DM / 128, SEQ / 64), 256, SMEM_64>>>(
        BF_G, N_G, BF_W_DOWN, N_W_DOWN, nullptr, OFF_X1, out, 0, 0, 1, SEQ, DM, FFN);
}

// round 14
// speedup vs baseline: 1.2035x; 1.2035x over previous
#include <cuda_runtime.h>
#include <cuda_fp16.h>
#include <math.h>
#include <stdint.h>

// ---------------- problem constants ----------------
#define SEQ     2048
#define DM      768
#define DIP     3224
#define DINNER  1536
#define CONVCH  1664
#define NHEADS  24
#define HD      64
#define DSTATE  64
#define DCONV   4
#define FFN     2048
#define EPS1    1.1920929e-07f
#define EPSG    1e-5f

// ---------------- fp32 scratch arena ----------------
constexpr size_t SZ_XN  = (size_t)SEQ * DM;
constexpr size_t SZ_ZX  = (size_t)SEQ * DIP;
constexpr size_t SZ_XBC = (size_t)SEQ * CONVCH;
constexpr size_t SZ_DT  = (size_t)SEQ * NHEADS;
constexpr size_t SZ_DA  = (size_t)SEQ * NHEADS;
constexpr size_t SZ_Y   = (size_t)SEQ * DINNER;
constexpr size_t SZ_G   = (size_t)SEQ * FFN;

constexpr size_t OFF_XN  = 0;
constexpr size_t OFF_ZX  = OFF_XN  + SZ_XN;
constexpr size_t OFF_XBC = OFF_ZX  + SZ_ZX;
constexpr size_t OFF_DT  = OFF_XBC + SZ_XBC;
constexpr size_t OFF_DA  = OFF_DT  + SZ_DT;
constexpr size_t OFF_Y   = OFF_DA  + SZ_DA;
constexpr size_t OFF_X1  = OFF_Y   + SZ_Y;
constexpr size_t OFF_H   = OFF_X1  + SZ_XN;
constexpr size_t OFF_G   = OFF_H   + SZ_XN;
constexpr size_t TOTAL_F = OFF_G   + SZ_G;

__device__ float g_buf[TOTAL_F];

// ---------------- fp16 arena: weights single, activations hi/lo ----------------
constexpr size_t N_W_IN   = (size_t)DIP * DM;
constexpr size_t N_W_OUT  = (size_t)DM * DINNER;
constexpr size_t N_W_GATE = (size_t)FFN * DM;
constexpr size_t N_W_UP   = (size_t)FFN * DM;
constexpr size_t N_W_DOWN = (size_t)DM * FFN;
constexpr size_t N_XN = SZ_XN;
constexpr size_t N_Y  = SZ_Y;
constexpr size_t N_H  = SZ_XN;
constexpr size_t N_G  = SZ_G;

constexpr size_t HF_W_IN   = 0;
constexpr size_t HF_W_OUT  = HF_W_IN   + N_W_IN;
constexpr size_t HF_W_GATE = HF_W_OUT  + N_W_OUT;
constexpr size_t HF_W_UP   = HF_W_GATE + N_W_GATE;
constexpr size_t HF_W_DOWN = HF_W_UP   + N_W_UP;
constexpr size_t HF_XN     = HF_W_DOWN + N_W_DOWN;
constexpr size_t HF_Y      = HF_XN     + 2 * N_XN;
constexpr size_t HF_H      = HF_Y      + 2 * N_Y;
constexpr size_t HF_G      = HF_H      + 2 * N_H;
constexpr size_t TOTAL_HF  = HF_G      + 2 * N_G;

__device__ __align__(256) __half g_hf[TOTAL_HF];

__device__ __forceinline__ const float* RP(const float* p, size_t off) {
    return p ? p : (const float*)g_buf + off;
}
__device__ __forceinline__ float* WP(float* p, size_t off) {
    return p ? p : g_buf + off;
}
__device__ __forceinline__ float siluf(float v) { return v / (1.0f + expf(-v)); }

__device__ __forceinline__ void h_split(float x, __half& h, __half& l) {
    h = __float2half_rn(x);
    l = __float2half_rn(x - __half2float(h));
}

// ---------------- PTX helpers ----------------
__device__ __forceinline__ uint32_t smem_u32(const void* p) {
    uint32_t a;
    asm("{ .reg .u64 t; cvta.to.shared.u64 t, %1; cvt.u32.u64 %0, t; }" : "=r"(a) : "l"(p));
    return a;
}
#define CP_ASYNC16(dst, src, sz) \
    asm volatile("cp.async.cg.shared.global [%0], [%1], 16, %2;" \
        :: "r"(dst), "l"(src), "r"(sz) : "memory")
#define CP_COMMIT() asm volatile("cp.async.commit_group;" ::: "memory")
#define CP_WAITG(n) asm volatile("cp.async.wait_group %0;" :: "n"(n) : "memory")

__device__ __forceinline__ void ldsm4(uint32_t* r, uint32_t addr) {
    asm volatile("ldmatrix.sync.aligned.m8n8.x4.shared.b16 {%0,%1,%2,%3}, [%4];"
        : "=r"(r[0]), "=r"(r[1]), "=r"(r[2]), "=r"(r[3]) : "r"(addr));
}
__device__ __forceinline__ void mma16(float (&c)[4], const uint32_t* a,
                                      uint32_t b0, uint32_t b1) {
    asm volatile(
        "mma.sync.aligned.m16n8k16.row.col.f32.f16.f16.f32 "
        "{%0,%1,%2,%3},{%4,%5,%6,%7},{%8,%9},{%0,%1,%2,%3};"
        : "+f"(c[0]), "+f"(c[1]), "+f"(c[2]), "+f"(c[3])
        : "r"(a[0]), "r"(a[1]), "r"(a[2]), "r"(a[3]), "r"(b0), "r"(b1));
}

// ---------------- fp32 -> fp16 single (weights) ----------------
__global__ __launch_bounds__(256) void f2h_kernel(
    const float* __restrict__ src4, size_t hfoff, size_t n)
{
    const float4* src = (const float4*)src4;
    __half* dst = g_hf + hfoff;
    size_t n4 = n >> 2;
    for (size_t i = (size_t)blockIdx.x * 256 + threadIdx.x; i < n4;
         i += (size_t)gridDim.x * 256) {
        float4 v = src[i];
        ushort4 o;
        o.x = __half_as_ushort(__float2half_rn(v.x));
        o.y = __half_as_ushort(__float2half_rn(v.y));
        o.z = __half_as_ushort(__float2half_rn(v.z));
        o.w = __half_as_ushort(__float2half_rn(v.w));
        ((ushort4*)dst)[i] = o;
    }
}

// ---------------- block reduce ----------------
__device__ __forceinline__ float blockReduceSum(float v) {
    __shared__ float sh[32];
    int lane = threadIdx.x & 31, wid = threadIdx.x >> 5;
    #pragma unroll
    for (int o = 16; o; o >>= 1) v += __shfl_xor_sync(0xffffffffu, v, o);
    if (lane == 0) sh[wid] = v;
    __syncthreads();
    if (wid == 0) {
        v = (lane < (int)(blockDim.x >> 5)) ? sh[lane] : 0.0f;
        #pragma unroll
        for (int o = 16; o; o >>= 1) v += __shfl_xor_sync(0xffffffffu, v, o);
        if (lane == 0) sh[0] = v;
    }
    __syncthreads();
    return sh[0];
}

// ---------------- RMSNorm (optional fused fp16 hi/lo output) ----------------
__global__ __launch_bounds__(256) void rmsnorm_kernel(
    const float* __restrict__ xe, size_t xoff,
    const float* __restrict__ w,
    float* __restrict__ oe, size_t ooff,
    size_t hfoff, size_t hfn,
    int C, float eps)
{
    const float* x = RP(xe, xoff) + (size_t)blockIdx.x * C;
    float* o = WP(oe, ooff) + (size_t)blockIdx.x * C;
    float ss = 0.0f;
    for (int i = threadIdx.x; i < C; i += 256) { float v = x[i]; ss += v * v; }
    float tot = blockReduceSum(ss);
    float scale = rsqrtf(tot / (float)C + eps);
    __half* hi = g_hf + hfoff + (size_t)blockIdx.x * C;
    __half* lo = hi + hfn;
    for (int i = threadIdx.x; i < C; i += 256) {
        float v = x[i] * scale * w[i];
        o[i] = v;
        if (hfn) { __half h, l; h_split(v, h, l); hi[i] = h; lo[i] = l; }
    }
}

// ---------------- Gated RMSNorm -> fp16 hi/lo y ----------------
__global__ __launch_bounds__(256) void gated_norm_kernel(const float* __restrict__ w)
{
    __shared__ float sv[DINNER];
    size_t r = blockIdx.x;
    const float* y = g_buf + OFF_Y + r * DINNER;
    const float* z = g_buf + OFF_ZX + r * DIP;
    float ss = 0.0f;
    for (int i = threadIdx.x; i < DINNER; i += 256) {
        float v = y[i] * siluf(z[i]);
        sv[i] = v;
        ss += v * v;
    }
    float tot = blockReduceSum(ss);
    float scale = rsqrtf(tot / (float)DINNER + EPSG);
    __half* hi = g_hf + HF_Y + r * DINNER;
    __half* lo = hi + N_Y;
    for (int i = threadIdx.x; i < DINNER; i += 256) {
        float v = sv[i] * scale * w[i];
        __half h, l; h_split(v, h, l);
        hi[i] = h; lo[i] = l;
    }
}

// ---------------- causal depthwise conv4 + bias + SiLU ----------------
__global__ __launch_bounds__(256) void conv_silu_kernel(
    const float* __restrict__ cw, const float* __restrict__ cb)
{
    int gid = blockIdx.x * 256 + threadIdx.x;
    if (gid >= SEQ * CONVCH) return;
    int c = gid % CONVCH;
    int t = gid / CONVCH;
    const float* zx = g_buf + OFF_ZX;
    float v = cb[c];
    #pragma unroll
    for (int k = 0; k < DCONV; k++) {
        int tt = t + k - (DCONV - 1);
        if (tt >= 0) v += zx[(size_t)tt * DIP + DINNER + c] * cw[c * DCONV + k];
    }
    g_buf[OFF_XBC + (size_t)t * CONVCH + c] = siluf(v);
}

// ---------------- dt in exact fp32 (error-amplifying path) ----------------
__global__ __launch_bounds__(128) void dtprep_kernel(
    const float* __restrict__ W, const float* __restrict__ dt_bias,
    const float* __restrict__ A_log)
{
    int t = blockIdx.x;
    int lane = threadIdx.x & 31, w = threadIdx.x >> 5;
    const float4* xn = (const float4*)(g_buf + OFF_XN + (size_t)t * DM);
    for (int h = w; h < NHEADS; h += 4) {
        const float4* wr = (const float4*)(W + (size_t)(DINNER + CONVCH + h) * DM);
        float s = 0.f;
        for (int i = lane; i < DM / 4; i += 32) {
            float4 a = xn[i], b = wr[i];
            s += a.x * b.x + a.y * b.y + a.z * b.z + a.w * b.w;
        }
        #pragma unroll
        for (int o = 16; o; o >>= 1) s += __shfl_xor_sync(0xffffffffu, s, o);
        if (lane == 0) {
            float v = s + dt_bias[h];
            float dt = (v > 20.f) ? v : log1pf(expf(v));
            g_buf[OFF_DT + (size_t)t * NHEADS + h] = dt;
            g_buf[OFF_DA + (size_t)t * NHEADS + h] = expf(dt * (-expf(A_log[h])));
        }
    }
}

// ---------------- SSM scan (register pipelined, barrier-free) ----------------
__global__ __launch_bounds__(256) void scan_kernel(const float* __restrict__ Dv)
{
    const int b   = blockIdx.x;
    const int h   = b >> 2;
    const int ps  = b & 3;
    const int tid = threadIdx.x;
    const int pl  = tid >> 4;
    const int nq  = tid & 15;
    const int p   = ps * 16 + pl;
    const int n0  = nq * 4;
    const float Dh = Dv[h];

    const float* xbc = g_buf + OFF_XBC;
    const float* dtb = g_buf + OFF_DT;
    const float* dab = g_buf + OFF_DA;
    float* yb = g_buf + OFF_Y;

    const float* Bcol = xbc + DINNER + n0;
    const float* Ccol = xbc + DINNER + DSTATE + n0;
    const float* Xcol = xbc + h * HD + p;

    constexpr int PF = 8;
    float4 rB[PF], rC[PF];
    float rx[PF], rdt[PF], rdA[PF];

    #pragma unroll
    for (int i = 0; i < PF; i++) {
        rB[i]  = *(const float4*)(Bcol + (size_t)i * CONVCH);
        rC[i]  = *(const float4*)(Ccol + (size_t)i * CONVCH);
        rx[i]  = Xcol[(size_t)i * CONVCH];
        rdt[i] = dtb[(size_t)i * NHEADS + h];
        rdA[i] = dab[(size_t)i * NHEADS + h];
    }

    float s0 = 0.f, s1 = 0.f, s2 = 0.f, s3 = 0.f;
    const bool writer = (nq == 0);

    for (int t = 0; t < SEQ; t += PF) {
        #pragma unroll
        for (int u = 0; u < PF; u++) {
            float dA = rdA[u], dt = rdt[u], x = rx[u];
            float4 Bv = rB[u], Cv = rC[u];
            int tn = t + u + PF;
            if (tn < SEQ) {
                rB[u]  = *(const float4*)(Bcol + (size_t)tn * CONVCH);
                rC[u]  = *(const float4*)(Ccol + (size_t)tn * CONVCH);
                rx[u]  = Xcol[(size_t)tn * CONVCH];
                rdt[u] = dtb[(size_t)tn * NHEADS + h];
                rdA[u] = dab[(size_t)tn * NHEADS + h];
            }
            float dtx = dt * x;
            s0 = s0 * dA + dtx * Bv.x; float acc = s0 * Cv.x;
            s1 = s1 * dA + dtx * Bv.y; acc += s1 * Cv.y;
            s2 = s2 * dA + dtx * Bv.z; acc += s2 * Cv.z;
            s3 = s3 * dA + dtx * Bv.w; acc += s3 * Cv.w;
            acc += __shfl_xor_sync(0xffffffffu, acc, 1);
            acc += __shfl_xor_sync(0xffffffffu, acc, 2);
            acc += __shfl_xor_sync(0xffffffffu, acc, 4);
            acc += __shfl_xor_sync(0xffffffffu, acc, 8);
            if (writer)
                yb[(size_t)(t + u) * DINNER + h * HD + p] = acc + Dh * x;
        }
    }
}

// ---------------- asymmetric fp16 HMMA GEMM ----------------
// O[M,N] = A[M,K] @ W[N,K]^T, A = Ah+Al (fp16 pair, ~exact), W single fp16.
// 2 MMAs per tile (acc += Ah*W; acc += Al*W). 4-stage cp.async, 1 sync/chunk.
// modes: 0 = fp32 out, 1 = fp32 out + residual, 2 = swiglu epilogue -> fp16 hi/lo.
#define RS 80
#define NSTG 4

template<int BM>
__global__ __launch_bounds__(256) void gemm_hf(
    size_t a_hi, size_t a_n,
    size_t w_off,
    const float* __restrict__ Re, size_t roff,
    float* __restrict__ Oe, size_t ooff, size_t hfn,
    int mode, int M, int N, int K)
{
    constexpr int TI = BM / 32;
    constexpr int ABUF = BM * RS;
    constexpr int BBUF = 128 * RS;
    constexpr int STAGE = 2 * ABUF + BBUF;

    extern __shared__ char smem[];
    const uint32_t sb = smem_u32(smem);
    const int tid  = threadIdx.x;
    const int lane = tid & 31;
    const int wid  = tid >> 5;
    const int wm   = (wid & 1) * (BM / 2);
    const int wn   = (wid >> 1) * 32;
    const int bm   = blockIdx.y * BM;
    const int bn   = blockIdx.x * 128;
    const int g    = lane >> 2;
    const int cc   = lane & 3;

    const __half* Ah = g_hf + a_hi;
    const __half* Al = Ah + a_n;
    const __half* Wm = g_hf + w_off;

    const int l15 = lane & 15;
    const int lhi = (lane >> 4) & 1;
    const uint32_t aoff = (uint32_t)((wm + l15) * RS + lhi * 16);
    const uint32_t boff = (uint32_t)(2 * ABUF + (wn + l15) * RS + lhi * 16);

    float acc[TI][4][4];
    #pragma unroll
    for (int i = 0; i < TI; i++)
        #pragma unroll
        for (int j = 0; j < 4; j++)
            #pragma unroll
            for (int q = 0; q < 4; q++) acc[i][j][q] = 0.f;

    const int KT = K >> 5;

    auto issue = [&](int kc) {
        const uint32_t base = sb + (uint32_t)(kc & (NSTG - 1)) * STAGE;
        const size_t kb = (size_t)kc * 32;
        #pragma unroll
        for (int u = tid; u < BM * 4; u += 256) {
            int row = u >> 2, un = u & 3;
            uint32_t d = base + (uint32_t)(row * RS + un * 16);
            size_t gs = (size_t)(bm + row) * K + kb + un * 8;
            CP_ASYNC16(d, Ah + gs, 16);
            CP_ASYNC16(d + ABUF, Al + gs, 16);
        }
        #pragma unroll
        for (int u = tid; u < 512; u += 256) {
            int row = u >> 2, un = u & 3;
            int n = bn + row;
            int sz = (n < N) ? 16 : 0;
            size_t gs = (n < N) ? ((size_t)n * K + kb + un * 8) : 0;
            uint32_t d = base + (uint32_t)(2 * ABUF + row * RS + un * 16);
            CP_ASYNC16(d, Wm + gs, sz);
        }
        CP_COMMIT();
    };

    issue(0); issue(1); issue(2);

    for (int kc = 0; kc < KT; kc++) {
        if (kc == KT - 1)      { CP_WAITG(0); }
        else if (kc == KT - 2) { CP_WAITG(1); }
        else                   { CP_WAITG(2); }
        __syncthreads();
        if (kc + 3 < KT) issue(kc + 3);

        const uint32_t base = sb + (uint32_t)(kc & (NSTG - 1)) * STAGE;
        #pragma unroll
        for (int s = 0; s < 2; s++) {
            uint32_t ah[TI][4], al[TI][4], bw[2][4];
            #pragma unroll
            for (int i = 0; i < TI; i++) {
                uint32_t ad = base + aoff + i * (16 * RS) + s * 32;
                ldsm4(ah[i], ad);
                ldsm4(al[i], ad + ABUF);
            }
            #pragma unroll
            for (int jp = 0; jp < 2; jp++) {
                uint32_t bd = base + boff + jp * (16 * RS) + s * 32;
                ldsm4(bw[jp], bd);
            }
            #pragma unroll
            for (int i = 0; i < TI; i++) {
                #pragma unroll
                for (int j = 0; j < 4; j++) {
                    int jp = j >> 1, sel = j & 1;
                    uint32_t b0 = bw[jp][sel], b1 = bw[jp][sel + 2];
                    mma16(acc[i][j], ah[i], b0, b1);
                    mma16(acc[i][j], al[i], b0, b1);
                }
            }
        }
    }

    // ---- epilogue ----
    if (mode == 2) {
        const float* G = RP(Re, roff);
        __half* hi = g_hf + ooff;
        __half* lo = hi + hfn;
        #pragma unroll
        for (int i = 0; i < TI; i++) {
            int row = bm + wm + i * 16 + g;
            #pragma unroll
            for (int j = 0; j < 4; j++) {
                int col = bn + wn + j * 8 + 2 * cc;
                if (col < N) {
                    #pragma unroll
                    for (int half = 0; half < 2; half++) {
                        int r = row + half * 8;
                        size_t o = (size_t)r * N + col;
                        float2 gv = *(const float2*)(G + o);
                        float v0 = siluf(gv.x) * acc[i][j][half * 2 + 0];
                        float v1 = siluf(gv.y) * acc[i][j][half * 2 + 1];
                        __half h0, l0, h1, l1;
                        h_split(v0, h0, l0); h_split(v1, h1, l1);
                        *(__half2*)(hi + o) = __half2(h0, h1);
                        *(__half2*)(lo + o) = __half2(l0, l1);
                    }
                }
            }
        }
    } else {
        const float* R = (mode == 1) ? RP(Re, roff) : nullptr;
        float* O = WP(Oe, ooff);
        #pragma unroll
        for (int i = 0; i < TI; i++) {
            int row = bm + wm + i * 16 + g;
            #pragma unroll
            for (int j = 0; j < 4; j++) {
                int col = bn + wn + j * 8 + 2 * cc;
                if (col < N) {
                    size_t o0 = (size_t)row * N + col;
                    size_t o1 = (size_t)(row + 8) * N + col;
                    float2 v0 = make_float2(acc[i][j][0], acc[i][j][1]);
                    float2 v1 = make_float2(acc[i][j][2], acc[i][j][3]);
                    if (mode == 1) {
                        float2 q0 = *(const float2*)(R + o0);
                        float2 q1 = *(const float2*)(R + o1);
                        v0.x += q0.x; v0.y += q0.y;
                        v1.x += q1.x; v1.y += q1.y;
                    }
                    *(float2*)(O + o0) = v0;
                    *(float2*)(O + o1) = v1;
                }
            }
        }
    }
}

constexpr int SMEM_128 = NSTG * (2 * 128 * RS + 128 * RS);  // 122880
constexpr int SMEM_64  = NSTG * (2 * 64 * RS + 128 * RS);   // 81920

// ---------------- launch ----------------
extern "C" void kernel_launch(void* const* d_in, const int* in_sizes, int n_in,
                              void* d_out, int out_size)
{
    const float* x          = (const float*)d_in[0];
    const float* norm1_w    = (const float*)d_in[1];
    const float* norm2_w    = (const float*)d_in[2];
    const float* in_proj_w  = (const float*)d_in[3];
    const float* conv_w     = (const float*)d_in[4];
    const float* conv_b     = (const float*)d_in[5];
    const float* dt_bias    = (const float*)d_in[6];
    const float* A_log      = (const float*)d_in[7];
    const float* Dv         = (const float*)d_in[8];
    const float* ssm_norm_w = (const float*)d_in[9];
    const float* out_proj_w = (const float*)d_in[10];
    const float* gate_w     = (const float*)d_in[11];
    const float* up_w       = (const float*)d_in[12];
    const float* down_w     = (const float*)d_in[13];
    float* out = (float*)d_out;

    cudaFuncSetAttribute(gemm_hf<128>, cudaFuncAttributeMaxDynamicSharedMemorySize, SMEM_128);
    cudaFuncSetAttribute(gemm_hf<64>,  cudaFuncAttributeMaxDynamicSharedMemorySize, SMEM_64);

    // launches 1-5 (ncu -s 5 -c 1 profiles launch #6 = in_proj GEMM)
    rmsnorm_kernel<<<SEQ, 256>>>(x, 0, norm1_w, nullptr, OFF_XN, HF_XN, N_XN, DM, EPS1);
    f2h_kernel<<<256, 256>>>(in_proj_w,  HF_W_IN,   N_W_IN);
    f2h_kernel<<<128, 256>>>(out_proj_w, HF_W_OUT,  N_W_OUT);
    f2h_kernel<<<160, 256>>>(gate_w,     HF_W_GATE, N_W_GATE);
    f2h_kernel<<<160, 256>>>(up_w,       HF_W_UP,   N_W_UP);

    // #6: zxbcdt = xn @ in_proj_w^T
    gemm_hf<128><<<dim3((DIP + 127) / 128, SEQ / 128), 256, SMEM_128>>>(
        HF_XN, N_XN, HF_W_IN, nullptr, 0, nullptr, OFF_ZX, 0, 0, SEQ, DIP, DM);

    f2h_kernel<<<160, 256>>>(down_w, HF_W_DOWN, N_W_DOWN);

    // conv + silu
    conv_silu_kernel<<<(SEQ * CONVCH + 255) / 256, 256>>>(conv_w, conv_b);

    // dt exact fp32 + dA
    dtprep_kernel<<<SEQ, 128>>>(in_proj_w, dt_bias, A_log);

    // SSM scan
    scan_kernel<<<NHEADS * 4, 256>>>(Dv);

    // gated rmsnorm -> fp16 hi/lo y
    gated_norm_kernel<<<SEQ, 256>>>(ssm_norm_w);

    // x1 = y @ out_proj_w^T + x
    gemm_hf<64><<<dim3(DM / 128, SEQ / 64), 256, SMEM_64>>>(
        HF_Y, N_Y, HF_W_OUT, x, 0, nullptr, OFF_X1, 0, 1, SEQ, DM, DINNER);

    // h = rmsnorm(x1) -> fp16 hi/lo
    rmsnorm_kernel<<<SEQ, 256>>>(nullptr, OFF_X1, norm2_w, nullptr, OFF_H, HF_H, N_H, DM, EPS1);

    // g = h @ gate_w^T (fp32)
    gemm_hf<128><<<dim3(FFN / 128, SEQ / 128), 256, SMEM_128>>>(
        HF_H, N_H, HF_W_GATE, nullptr, 0, nullptr, OFF_G, 0, 0, SEQ, FFN, DM);

    // u = h @ up_w^T, fused: hfG = split(silu(g) * u)
    gemm_hf<128><<<dim3(FFN / 128, SEQ / 128), 256, SMEM_128>>>(
        HF_H, N_H, HF_W_UP, nullptr, OFF_G, nullptr, HF_G, N_G, 2, SEQ, FFN, DM);

    // out = hfG @ down_w^T + x1
    gemm_hf<64><<<dim3(DM / 128, SEQ / 64), 256, SMEM_64>>>(
        HF_G, N_G, HF_W_DOWN, nullptr, OFF_X1, out, 0, 0, 1, SEQ, DM, FFN);
}